// round 11
// baseline (speedup 1.0000x reference)
#include <cuda_runtime.h>
#include <cuda_fp16.h>
#include <cstdint>

// DepthConv: out[b,o,p] = sum_t gate[b,t,p] * sum_c w[t,o,c]*x[b,c,p+shift(t)]
// R7 hot loop (champion: f32-acc mma, HMUL2 gating, spread cp.async B staging)
// + IN-KERNEL x fp32->fp16 halo staging: LDG.128 from native x[c][p], 4x4
// register transpose + cvt, STS.64 into the [p][c] halo. Kills the 13us
// x-conversion prepass entirely.

#define ALPHA_F 8.3f

constexpr int Bn = 8;
constexpr int Cn = 512;
constexpr int Hn = 64;
constexpr int Wn = 64;
constexpr int On = 64;
constexpr int PIXn = Hn * Wn;       // 4096

constexpr int Mt = 128;             // pixels per CTA (8 rows x 16 cols)
constexpr int KC = 64;              // c-chunk per epoch
constexpr int EPOCHS = Cn / KC;     // 8
constexpr int NIT = EPOCHS * 9;     // 72 (epoch-major, tap-minor)
constexpr int HS = 72;              // halo row stride in halves (64 + 8 pad)

// ---- device-global scratch (weights only now) ----
__device__ __half g_wh[9 * On * Cn];              // [tap][o][c]  fp16

// ---- smem layout (bytes) ----
constexpr int HBUF = 180 * HS * 2;           // 25920 (x2 buffers)
constexpr int BBUF = On * HS * 2;            // 9216  (x3 buffers)
constexpr int OFF_H = 0;
constexpr int OFF_B = 2 * HBUF;              // 51840
constexpr int OFF_G = OFF_B + 3 * BBUF;      // 79488 gates 9*128*4
constexpr int SMEM_TOTAL = OFF_G + 9 * Mt * 4;  // 84096 -> 2 CTAs/SM

// ====================== helpers ======================
__device__ __forceinline__ uint32_t smem_u32(const void* p) {
    uint32_t a;
    asm("{ .reg .u64 t; cvta.to.shared.u64 t, %1; cvt.u32.u64 %0, t; }"
        : "=r"(a) : "l"(p));
    return a;
}
__device__ __forceinline__ void ldsm_x4(uint32_t* r, uint32_t addr) {
    asm volatile("ldmatrix.sync.aligned.m8n8.x4.shared.b16 {%0,%1,%2,%3}, [%4];"
        : "=r"(r[0]), "=r"(r[1]), "=r"(r[2]), "=r"(r[3]) : "r"(addr));
}
__device__ __forceinline__ void mma16816(float* c, const uint32_t* a,
                                         uint32_t b0, uint32_t b1) {
    asm volatile(
        "mma.sync.aligned.m16n8k16.row.col.f32.f16.f16.f32 "
        "{%0,%1,%2,%3}, {%4,%5,%6,%7}, {%8,%9}, {%0,%1,%2,%3};"
        : "+f"(c[0]), "+f"(c[1]), "+f"(c[2]), "+f"(c[3])
        : "r"(a[0]), "r"(a[1]), "r"(a[2]), "r"(a[3]), "r"(b0), "r"(b1));
}
__device__ __forceinline__ uint32_t hmul2u(uint32_t a, uint32_t g) {
    __half2 r = __hmul2(*reinterpret_cast<__half2*>(&a),
                        *reinterpret_cast<__half2*>(&g));
    return *reinterpret_cast<uint32_t*>(&r);
}
#define CP_ASYNC16(dst, src) \
    asm volatile("cp.async.cg.shared.global [%0], [%1], 16;" \
                 :: "r"(dst), "l"(src) : "memory")
#define CP_COMMIT() asm volatile("cp.async.commit_group;" ::: "memory")
#define CP_WAIT1()  asm volatile("cp.async.wait_group 1;" ::: "memory")
#define CP_WAIT0()  asm volatile("cp.async.wait_group 0;" ::: "memory")

// ====================== weight pre-pass (tiny) ======================
constexpr int NW_ELEM = 9 * On * Cn;                   // 294912
constexpr int NW_BLK = NW_ELEM / (256 * 8);            // 144

__global__ __launch_bounds__(256) void prep_w(const float* __restrict__ w) {
    const int base = blockIdx.x * 2048 + threadIdx.x;
    #pragma unroll
    for (int j = 0; j < 8; j++) {
        const int idx = base + j * 256;          // [t][o][c]
        const int c = idx % Cn;
        const int o = (idx / Cn) % On;
        const int t = idx / (Cn * On);
        g_wh[idx] = __float2half_rn(w[((size_t)o * Cn + c) * 9 + t]);
    }
}

// ====================== main kernel ======================
__global__ __launch_bounds__(256, 2) void depthconv_mma(
    const float* __restrict__ xg,
    const float* __restrict__ depth,
    float* __restrict__ out)
{
    extern __shared__ __align__(16) char smem[];
    const uint32_t sb = smem_u32(smem);
    uint32_t* g_sp = reinterpret_cast<uint32_t*>(smem + OFF_G);  // [9][128] half2

    const int tid = threadIdx.x;
    const int wid = tid >> 5;
    const int lid = tid & 31;

    const int blk = blockIdx.x;          // 0..255
    const int b   = blk >> 5;
    const int tl  = blk & 31;
    const int h0  = (tl >> 2) * 8;       // 8 pixel rows
    const int w0  = (tl & 3) * 16;       // 16 pixel cols

    // ---- gates: 9 taps x 128 pixels, stored as (g,g) half2 ----
    if (tid < Mt) {
        const int hh = h0 + (tid >> 4);
        const int ww = w0 + (tid & 15);
        const float* dptr = depth + b * PIXn;
        const float d0 = dptr[hh * Wn + ww];
        #pragma unroll
        for (int t = 0; t < 9; t++) {
            const int h2 = hh + t / 3 - 1, w2 = ww + t % 3 - 1;
            float g = 0.f;
            if (h2 >= 0 && h2 < Hn && w2 >= 0 && w2 < Wn)
                g = __expf(-ALPHA_F * fabsf(d0 - dptr[h2 * Wn + w2]));
            const __half gh = __float2half_rn(g);
            __half2 gp = __halves2half2(gh, gh);
            g_sp[t * Mt + tid] = *reinterpret_cast<uint32_t*>(&gp);
        }
    }

    // ---- in-kernel halo staging setup ----
    // Units: (c4 0..15, hr 0..9, j4 0..5) = 960; thread handles tid + k*256.
    // Unit: load 4 LDG.128 (channels c4*4..+3, 4 pixels of the 24-float
    // aligned span [w0-4, w0+20) of halo row hr), 4x4 reg transpose + cvt,
    // up to 4 STS.64 into halo [ent][c].
    const float* xb = xg + (size_t)b * Cn * PIXn;
    const int nhk = (tid < 192) ? 4 : 3;   // 960 = 3*256 + 192
    int      hgb[4];     // gmem float offset (within image, epoch 0)
    int      hdst[4];    // halo byte offset of pp=0 entry (may be negative)
    uint32_t hmask[4];   // bit pp: store valid
    #pragma unroll
    for (int k = 0; k < 4; k++) {
        const int u = tid + k * 256;
        if (k < nhk) {
            const int c4 = u / 60;
            const int r  = u - c4 * 60;
            const int hr = r / 6;
            const int j4 = r - hr * 6;
            const int hh = min(max(h0 - 1 + hr, 0), Hn - 1);
            const int wj = min(max(w0 - 4 + 4 * j4, 0), 60);
            hgb[k]  = (c4 * 4) * PIXn + hh * Wn + wj;
            const int wc0 = 4 * j4 - 3;                 // wc of pp=0
            hdst[k] = (hr * 18 + wc0) * (HS * 2) + c4 * 8;
            uint32_t m = 0;
            #pragma unroll
            for (int pp = 0; pp < 4; pp++) {
                const int wc = wc0 + pp;
                if (wc >= 0 && wc < 18) m |= (1u << pp);
            }
            hmask[k] = m;
        } else { hgb[k] = 0; hdst[k] = 0; hmask[k] = 0; }
    }

    auto stage_halo = [&](int e, int buf, int kf, int kt) {
        const int ebase = e * KC * PIXn;
        char* hb = smem + OFF_H + buf * HBUF;
        #pragma unroll
        for (int k = 0; k < 4; k++) {
            if (k < kf || k >= kt || k >= nhk) continue;
            const float* src = xb + ebase + hgb[k];
            float4 f0 = *reinterpret_cast<const float4*>(src);
            float4 f1 = *reinterpret_cast<const float4*>(src + PIXn);
            float4 f2 = *reinterpret_cast<const float4*>(src + 2 * PIXn);
            float4 f3 = *reinterpret_cast<const float4*>(src + 3 * PIXn);
            const uint32_t m = hmask[k];
            char* d = hb + hdst[k];
            if (m & 1u) {
                uint2 v;
                __half2 a = __floats2half2_rn(f0.x, f1.x);
                __half2 c = __floats2half2_rn(f2.x, f3.x);
                v.x = *reinterpret_cast<uint32_t*>(&a);
                v.y = *reinterpret_cast<uint32_t*>(&c);
                *reinterpret_cast<uint2*>(d) = v;
            }
            if (m & 2u) {
                uint2 v;
                __half2 a = __floats2half2_rn(f0.y, f1.y);
                __half2 c = __floats2half2_rn(f2.y, f3.y);
                v.x = *reinterpret_cast<uint32_t*>(&a);
                v.y = *reinterpret_cast<uint32_t*>(&c);
                *reinterpret_cast<uint2*>(d + HS * 2) = v;
            }
            if (m & 4u) {
                uint2 v;
                __half2 a = __floats2half2_rn(f0.z, f1.z);
                __half2 c = __floats2half2_rn(f2.z, f3.z);
                v.x = *reinterpret_cast<uint32_t*>(&a);
                v.y = *reinterpret_cast<uint32_t*>(&c);
                *reinterpret_cast<uint2*>(d + 2 * HS * 2) = v;
            }
            if (m & 8u) {
                uint2 v;
                __half2 a = __floats2half2_rn(f0.w, f1.w);
                __half2 c = __floats2half2_rn(f2.w, f3.w);
                v.x = *reinterpret_cast<uint32_t*>(&a);
                v.y = *reinterpret_cast<uint32_t*>(&c);
                *reinterpret_cast<uint2*>(d + 3 * HS * 2) = v;
            }
        }
    };

    // ---- B staging (cp.async, unchanged): 512 chunks -> 2 per thread ----
    uint32_t bsoff[2];
    int boff[2];
    #pragma unroll
    for (int j = 0; j < 2; j++) {
        const int i = tid + j * 256;
        const int o = i >> 3, seg = i & 7;
        boff[j]  = o * Cn + seg * 8;
        bsoff[j] = (uint32_t)(o * HS + seg * 8) * 2;
    }
    auto stage_B = [&](int it, int buf) {
        const int e = it / 9, t = it - e * 9;
        const uint32_t bd = sb + OFF_B + buf * BBUF;
        const __half* wsrc = g_wh + (size_t)t * On * Cn + e * KC;
        #pragma unroll
        for (int j = 0; j < 2; j++)
            CP_ASYNC16(bd + bsoff[j], (const char*)(wsrc + boff[j]));
    };

    // ---- warp tiling: 4 (m) x 2 (n) warps; warp tile 32x32 ----
    const int wm = (wid & 3) * 32;
    const int wn = (wid >> 2) * 32;

    uint32_t abase[2];                    // per-lane A ldmatrix base (tap 0)
    #pragma unroll
    for (int mb = 0; mb < 2; mb++) {
        const int m   = wm + mb * 16 + (lid & 15);
        const int ent = (m >> 4) * 18 + (m & 15);
        abase[mb] = sb + OFF_H + (uint32_t)(ent * HS) * 2 + (uint32_t)(lid >> 4) * 16;
    }
    uint32_t bbase[2];                    // per-lane B ldmatrix base
    {
        const int br = (lid & 7) + ((lid >> 4) << 3);
        const uint32_t bcol = (uint32_t)(((lid >> 3) & 1) << 3) * 2;
        #pragma unroll
        for (int np = 0; np < 2; np++)
            bbase[np] = sb + OFF_B + (uint32_t)((wn + np * 16 + br) * HS) * 2 + bcol;
    }
    const int grow = (lid >> 2);

    float facc[2][4][4];
    #pragma unroll
    for (int i = 0; i < 2; i++)
        #pragma unroll
        for (int j = 0; j < 4; j++)
            #pragma unroll
            for (int k = 0; k < 4; k++) facc[i][j][k] = 0.f;

    // ---- prologue: epoch-0 halo (plain stores) + B(0), B(1) ----
    stage_halo(0, 0, 0, 4);
    stage_B(0, 0); CP_COMMIT();
    stage_B(1, 1); CP_COMMIT();

    for (int it = 0; it < NIT; it++) {
        const int e = it / 9, t = it - e * 9;

        if (it >= NIT - 2) { CP_WAIT0(); } else { CP_WAIT1(); }
        __syncthreads();    // staged data (and, first iter, gates/halo) visible

        const int trow = t / 3, tcol = t - trow * 3;
        const uint32_t aoff = (uint32_t)(e & 1) * HBUF
                            + (uint32_t)((trow * 18 + tcol) * (HS * 2));
        const uint32_t boffb = (uint32_t)(it % 3) * BBUF;

        uint32_t g0[2], g1[2];
        #pragma unroll
        for (int mb = 0; mb < 2; mb++) {
            const int r = wm + mb * 16 + grow;
            g0[mb] = g_sp[t * Mt + r];
            g1[mb] = g_sp[t * Mt + r + 8];
        }

        #pragma unroll
        for (int ks = 0; ks < 4; ks++) {
            uint32_t af[2][4];
            #pragma unroll
            for (int mb = 0; mb < 2; mb++) {
                ldsm_x4(af[mb], abase[mb] + aoff + ks * 32);
                af[mb][0] = hmul2u(af[mb][0], g0[mb]);
                af[mb][1] = hmul2u(af[mb][1], g1[mb]);
                af[mb][2] = hmul2u(af[mb][2], g0[mb]);
                af[mb][3] = hmul2u(af[mb][3], g1[mb]);
            }
            uint32_t bf[2][4];
            #pragma unroll
            for (int np = 0; np < 2; np++)
                ldsm_x4(bf[np], bbase[np] + boffb + ks * 32);
            #pragma unroll
            for (int mb = 0; mb < 2; mb++)
                #pragma unroll
                for (int nb = 0; nb < 4; nb++)
                    mma16816(facc[mb][nb], af[mb],
                             bf[nb >> 1][(nb & 1) * 2],
                             bf[nb >> 1][(nb & 1) * 2 + 1]);
        }

        // ---- post-compute spread staging ----
        if (it + 2 < NIT) {
            stage_B(it + 2, (it + 2) % 3);
            CP_COMMIT();
        }
        // halo for next epoch: split across t==0 and t==1 (written 7+ barriers
        // before first use at epoch e+1)
        if (e + 1 < EPOCHS) {
            if (t == 0)      stage_halo(e + 1, (e + 1) & 1, 0, 2);
            else if (t == 1) stage_halo(e + 1, (e + 1) & 1, 2, 4);
        }
    }

    // ---- epilogue: D(m=pixel, n=o) -> out[b][o][h][w] ----
    float* ob = out + (size_t)b * On * PIXn;
    const int mrow = wm + (lid >> 2);
    const int ncol = wn + (lid & 3) * 2;
    #pragma unroll
    for (int mb = 0; mb < 2; mb++) {
        #pragma unroll
        for (int half_ = 0; half_ < 2; half_++) {
            const int m  = mrow + mb * 16 + half_ * 8;
            const int hh = h0 + (m >> 4);
            const int ww = w0 + (m & 15);
            const int pix = hh * Wn + ww;
            #pragma unroll
            for (int nb = 0; nb < 4; nb++) {
                const int o = ncol + nb * 8;
                ob[(size_t)o * PIXn + pix]       = facc[mb][nb][half_ * 2];
                ob[(size_t)(o + 1) * PIXn + pix] = facc[mb][nb][half_ * 2 + 1];
            }
        }
    }
}

// ====================== launch ======================
extern "C" void kernel_launch(void* const* d_in, const int* in_sizes, int n_in,
                              void* d_out, int out_size) {
    const float* x     = (const float*)d_in[0];   // (8,512,64,64)
    const float* depth = (const float*)d_in[1];   // (8,1,64,64)
    const float* w     = (const float*)d_in[2];   // (64,512,3,3)
    float* out = (float*)d_out;                   // (8,64,64,64)

    cudaFuncSetAttribute(depthconv_mma,
                         cudaFuncAttributeMaxDynamicSharedMemorySize,
                         SMEM_TOTAL);

    prep_w<<<NW_BLK, 256>>>(w);
    depthconv_mma<<<Bn * 32, 256, SMEM_TOTAL>>>(x, depth, out);
}

// round 15
// speedup vs baseline: 1.0215x; 1.0215x over previous
#include <cuda_runtime.h>
#include <cuda_fp16.h>
#include <cstdint>

// DepthConv: out[b,o,p] = sum_t gate[b,t,p] * sum_c w[t,o,c]*x[b,c,p+shift(t)]
// R7 champion hot loop (epoch-major halo staged once per epoch, per-tap
// spread cp.async B staging, 3-buffer B, HMUL2 fp16 gating, f32-acc mma).
// R12 edits: (1) wider prepass tiles w/ float4 reads; (2) smem-staged
// coalesced epilogue (64B full-sector STG.128 chunks).

#define ALPHA_F 8.3f

constexpr int Bn = 8;
constexpr int Cn = 512;
constexpr int Hn = 64;
constexpr int Wn = 64;
constexpr int On = 64;
constexpr int PIXn = Hn * Wn;       // 4096

constexpr int Mt = 128;             // pixels per CTA (8 rows x 16 cols)
constexpr int KC = 64;              // c-chunk per epoch
constexpr int EPOCHS = Cn / KC;     // 8
constexpr int NIT = EPOCHS * 9;     // 72 (epoch-major, tap-minor)
constexpr int HE = 180;             // halo entries (10 x 18)
constexpr int HS = 72;              // smem row stride in halves (64 + 8 pad)

// ---- device-global scratch ----
__device__ __half g_xh[(size_t)Bn * PIXn * Cn];   // [b][pixel][c] fp16
__device__ __half g_wh[9 * On * Cn];              // [tap][o][c]  fp16

// ---- smem layout (bytes) ----
constexpr int HBUF = HE * HS * 2;            // 25920 (x2 buffers)
constexpr int BBUF = On * HS * 2;            // 9216  (x3 buffers)
constexpr int OFF_H = 0;
constexpr int OFF_B = 2 * HBUF;              // 51840
constexpr int OFF_G = OFF_B + 3 * BBUF;      // 79488 gates 9*128*4
constexpr int SMEM_TOTAL = OFF_G + 9 * Mt * 4;  // 84096 -> 2 CTAs/SM
// epilogue staging aliases the halo region: 64 o x 132 floats = 33792 B < 2*HBUF

// ====================== helpers ======================
__device__ __forceinline__ uint32_t smem_u32(const void* p) {
    uint32_t a;
    asm("{ .reg .u64 t; cvta.to.shared.u64 t, %1; cvt.u32.u64 %0, t; }"
        : "=r"(a) : "l"(p));
    return a;
}
__device__ __forceinline__ void ldsm_x4(uint32_t* r, uint32_t addr) {
    asm volatile("ldmatrix.sync.aligned.m8n8.x4.shared.b16 {%0,%1,%2,%3}, [%4];"
        : "=r"(r[0]), "=r"(r[1]), "=r"(r[2]), "=r"(r[3]) : "r"(addr));
}
__device__ __forceinline__ void mma16816(float* c, const uint32_t* a,
                                         uint32_t b0, uint32_t b1) {
    asm volatile(
        "mma.sync.aligned.m16n8k16.row.col.f32.f16.f16.f32 "
        "{%0,%1,%2,%3}, {%4,%5,%6,%7}, {%8,%9}, {%0,%1,%2,%3};"
        : "+f"(c[0]), "+f"(c[1]), "+f"(c[2]), "+f"(c[3])
        : "r"(a[0]), "r"(a[1]), "r"(a[2]), "r"(a[3]), "r"(b0), "r"(b1));
}
__device__ __forceinline__ uint32_t hmul2u(uint32_t a, uint32_t g) {
    __half2 r = __hmul2(*reinterpret_cast<__half2*>(&a),
                        *reinterpret_cast<__half2*>(&g));
    return *reinterpret_cast<uint32_t*>(&r);
}
#define CP_ASYNC16(dst, src) \
    asm volatile("cp.async.cg.shared.global [%0], [%1], 16;" \
                 :: "r"(dst), "l"(src) : "memory")
#define CP_COMMIT() asm volatile("cp.async.commit_group;" ::: "memory")
#define CP_WAIT1()  asm volatile("cp.async.wait_group 1;" ::: "memory")
#define CP_WAIT0()  asm volatile("cp.async.wait_group 0;" ::: "memory")

// ====================== fused pre-pass ======================
// x part: 64c x 128p tiles; float4 reads (512B/warp-row), half2 writes
// (128B/warp-row). w part: [o][c][3][3] -> [t][o][c] fp16.
constexpr int NT_BLK = Bn * (Cn / 64) * (PIXn / 128);  // 2048
constexpr int NW_ELEM = 9 * On * Cn;                   // 294912
constexpr int NW_BLK = NW_ELEM / (256 * 8);            // 144

__global__ __launch_bounds__(256) void prep_all(const float* __restrict__ x,
                                                const float* __restrict__ w) {
    const int bi = blockIdx.x;
    if (bi < NT_BLK) {
        __shared__ float tile[64][129];
        const int b  = bi / ((Cn / 64) * (PIXn / 128));
        const int r  = bi % ((Cn / 64) * (PIXn / 128));
        const int c0 = (r / (PIXn / 128)) * 64;
        const int p0 = (r % (PIXn / 128)) * 128;
        const int lane = threadIdx.x & 31;
        const int wrp  = threadIdx.x >> 5;     // 0..7
        #pragma unroll
        for (int j = 0; j < 8; j++) {          // warp handles 8 c-rows
            const int c = wrp * 8 + j;
            const float4 v = *reinterpret_cast<const float4*>(
                &x[((size_t)(b * Cn + c0 + c)) * PIXn + p0 + lane * 4]);
            tile[c][lane * 4]     = v.x;
            tile[c][lane * 4 + 1] = v.y;
            tile[c][lane * 4 + 2] = v.z;
            tile[c][lane * 4 + 3] = v.w;
        }
        __syncthreads();
        #pragma unroll
        for (int j = 0; j < 16; j++) {         // warp handles 16 pixel-rows
            const int p = wrp * 16 + j;
            __half2 v = __floats2half2_rn(tile[lane * 2][p], tile[lane * 2 + 1][p]);
            *reinterpret_cast<__half2*>(
                &g_xh[((size_t)(b * PIXn + p0 + p)) * Cn + c0 + lane * 2]) = v;
        }
    } else {
        const int base = (bi - NT_BLK) * 2048 + threadIdx.x;
        #pragma unroll
        for (int j = 0; j < 8; j++) {
            const int idx = base + j * 256;          // [t][o][c]
            const int c = idx % Cn;
            const int o = (idx / Cn) % On;
            const int t = idx / (Cn * On);
            g_wh[idx] = __float2half_rn(w[((size_t)o * Cn + c) * 9 + t]);
        }
    }
}

// ====================== main kernel ======================
__global__ __launch_bounds__(256, 2) void depthconv_mma(
    const float* __restrict__ depth,
    float* __restrict__ out)
{
    extern __shared__ __align__(16) char smem[];
    const uint32_t sb = smem_u32(smem);
    uint32_t* g_sp = reinterpret_cast<uint32_t*>(smem + OFF_G);  // [9][128] half2

    const int tid = threadIdx.x;
    const int wid = tid >> 5;
    const int lid = tid & 31;

    const int blk = blockIdx.x;          // 0..255
    const int b   = blk >> 5;
    const int tl  = blk & 31;
    const int h0  = (tl >> 2) * 8;       // 8 pixel rows
    const int w0  = (tl & 3) * 16;       // 16 pixel cols

    // ---- gates: 9 taps x 128 pixels, stored as (g,g) half2 ----
    if (tid < Mt) {
        const int hh = h0 + (tid >> 4);
        const int ww = w0 + (tid & 15);
        const float* dptr = depth + b * PIXn;
        const float d0 = dptr[hh * Wn + ww];
        #pragma unroll
        for (int t = 0; t < 9; t++) {
            const int h2 = hh + t / 3 - 1, w2 = ww + t % 3 - 1;
            float g = 0.f;
            if (h2 >= 0 && h2 < Hn && w2 >= 0 && w2 < Wn)
                g = __expf(-ALPHA_F * fabsf(d0 - dptr[h2 * Wn + w2]));
            const __half gh = __float2half_rn(g);
            __half2 gp = __halves2half2(gh, gh);
            g_sp[t * Mt + tid] = *reinterpret_cast<uint32_t*>(&gp);
        }
    }

    // ---- halo staging slots (epoch-invariant addressing) ----
    const __half* xb = g_xh + (size_t)b * PIXn * Cn;
    const int nj = (tid < 160) ? 6 : 5;   // 1440 chunks over 256 threads
    int qoff[6];        // global half offset (add c0)
    uint32_t soff[6];   // smem byte offset within halo buffer
    #pragma unroll
    for (int j = 0; j < 6; j++) {
        const int i = tid + j * 256;
        const int ent = i >> 3, seg = i & 7;
        const int hr = ent / 18, hc = ent - hr * 18;
        const int hh = min(max(h0 - 1 + hr, 0), Hn - 1);
        const int ww = min(max(w0 - 1 + hc, 0), Wn - 1);
        qoff[j] = (hh * Wn + ww) * Cn + seg * 8;
        soff[j] = (uint32_t)(ent * HS + seg * 8) * 2;
    }
    // B staging: 64 rows x 8 segs = 512 chunks -> 2 per thread
    uint32_t bsoff[2];
    int boff[2];
    #pragma unroll
    for (int j = 0; j < 2; j++) {
        const int i = tid + j * 256;
        const int o = i >> 3, seg = i & 7;
        boff[j]  = o * Cn + seg * 8;              // add tap*On*Cn + c0
        bsoff[j] = (uint32_t)(o * HS + seg * 8) * 2;
    }

    auto stage_halo = [&](int e, int buf) {
        const int c0 = e * KC;
        const uint32_t hd = sb + OFF_H + buf * HBUF;
        #pragma unroll
        for (int j = 0; j < 6; j++)
            if (j < nj)
                CP_ASYNC16(hd + soff[j], (const char*)(xb + qoff[j] + c0));
    };
    auto stage_B = [&](int it, int buf) {
        const int e = it / 9, t = it - e * 9;
        const uint32_t bd = sb + OFF_B + buf * BBUF;
        const __half* wsrc = g_wh + (size_t)t * On * Cn + e * KC;
        #pragma unroll
        for (int j = 0; j < 2; j++)
            CP_ASYNC16(bd + bsoff[j], (const char*)(wsrc + boff[j]));
    };

    // ---- warp tiling: 4 (m) x 2 (n) warps; warp tile 32x32 ----
    const int wm = (wid & 3) * 32;
    const int wn = (wid >> 2) * 32;

    uint32_t abase[2];                    // per-lane A ldmatrix base (tap 0)
    #pragma unroll
    for (int mb = 0; mb < 2; mb++) {
        const int m   = wm + mb * 16 + (lid & 15);
        const int ent = (m >> 4) * 18 + (m & 15);
        abase[mb] = sb + OFF_H + (uint32_t)(ent * HS) * 2 + (uint32_t)(lid >> 4) * 16;
    }
    uint32_t bbase[2];                    // per-lane B ldmatrix base
    {
        const int br = (lid & 7) + ((lid >> 4) << 3);
        const uint32_t bcol = (uint32_t)(((lid >> 3) & 1) << 3) * 2;
        #pragma unroll
        for (int np = 0; np < 2; np++)
            bbase[np] = sb + OFF_B + (uint32_t)((wn + np * 16 + br) * HS) * 2 + bcol;
    }
    const int grow = (lid >> 2);          // gate row within warp m-block

    float facc[2][4][4];
    #pragma unroll
    for (int i = 0; i < 2; i++)
        #pragma unroll
        for (int j = 0; j < 4; j++)
            #pragma unroll
            for (int k = 0; k < 4; k++) facc[i][j][k] = 0.f;

    stage_halo(0, 0); stage_B(0, 0); CP_COMMIT();   // group: halo(0)+B(0)
    stage_B(1, 1); CP_COMMIT();                     // group: B(1)

    for (int it = 0; it < NIT; it++) {
        const int e = it / 9, t = it - e * 9;

        if (it >= NIT - 2) { CP_WAIT0(); } else { CP_WAIT1(); }
        __syncthreads();    // staged data (and, first iter, gates) visible

        const int trow = t / 3, tcol = t - trow * 3;
        const uint32_t aoff = (uint32_t)(e & 1) * HBUF
                            + (uint32_t)((trow * 18 + tcol) * (HS * 2));
        const uint32_t boffb = (uint32_t)(it % 3) * BBUF;

        uint32_t g0[2], g1[2];            // (g,g) half2 per fragment row
        #pragma unroll
        for (int mb = 0; mb < 2; mb++) {
            const int r = wm + mb * 16 + grow;
            g0[mb] = g_sp[t * Mt + r];
            g1[mb] = g_sp[t * Mt + r + 8];
        }

        #pragma unroll
        for (int ks = 0; ks < 4; ks++) {
            uint32_t af[2][4];
            #pragma unroll
            for (int mb = 0; mb < 2; mb++) {
                ldsm_x4(af[mb], abase[mb] + aoff + ks * 32);
                af[mb][0] = hmul2u(af[mb][0], g0[mb]);
                af[mb][1] = hmul2u(af[mb][1], g1[mb]);
                af[mb][2] = hmul2u(af[mb][2], g0[mb]);
                af[mb][3] = hmul2u(af[mb][3], g1[mb]);
            }
            uint32_t bf[2][4];
            #pragma unroll
            for (int np = 0; np < 2; np++)
                ldsm_x4(bf[np], bbase[np] + boffb + ks * 32);
            #pragma unroll
            for (int mb = 0; mb < 2; mb++)
                #pragma unroll
                for (int nb = 0; nb < 4; nb++)
                    mma16816(facc[mb][nb], af[mb],
                             bf[nb >> 1][(nb & 1) * 2],
                             bf[nb >> 1][(nb & 1) * 2 + 1]);
        }

        // ---- post-compute spread staging (round-7 pattern) ----
        if (it + 2 < NIT) {
            stage_B(it + 2, (it + 2) % 3);
            if (t == 0 && e + 1 < EPOCHS)
                stage_halo(e + 1, (e + 1) & 1);
            CP_COMMIT();
        }
    }

    // ---- epilogue: stage facc through smem, write 64B coalesced chunks ----
    __syncthreads();                      // all ldsm reads of halo done
    float* ep_s = reinterpret_cast<float*>(smem + OFF_H);   // [64 o][132]
    {
        const int mrow = wm + (lid >> 2);
        const int ncol = wn + (lid & 3) * 2;
        #pragma unroll
        for (int mb = 0; mb < 2; mb++) {
            #pragma unroll
            for (int half_ = 0; half_ < 2; half_++) {
                const int m = mrow + mb * 16 + half_ * 8;
                #pragma unroll
                for (int nb = 0; nb < 4; nb++) {
                    const int o = ncol + nb * 8;
                    ep_s[o * 132 + m]       = facc[mb][nb][half_ * 2];
                    ep_s[(o + 1) * 132 + m] = facc[mb][nb][half_ * 2 + 1];
                }
            }
        }
    }
    __syncthreads();
    {
        const int og = tid >> 2;          // 0..63
        const int q  = tid & 3;           // 16B quarter of a 64B w-chunk
        float* ob = out + (size_t)b * On * PIXn + (size_t)og * PIXn
                  + h0 * Wn + w0 + q * 4;
        const float* sr = ep_s + og * 132 + q * 4;
        #pragma unroll
        for (int j = 0; j < 8; j++) {     // 8 h-rows of the tile
            const float4 v = *reinterpret_cast<const float4*>(sr + j * 16);
            *reinterpret_cast<float4*>(ob + j * Wn) = v;
        }
    }
}

// ====================== launch ======================
extern "C" void kernel_launch(void* const* d_in, const int* in_sizes, int n_in,
                              void* d_out, int out_size) {
    const float* x     = (const float*)d_in[0];   // (8,512,64,64)
    const float* depth = (const float*)d_in[1];   // (8,1,64,64)
    const float* w     = (const float*)d_in[2];   // (64,512,3,3)
    float* out = (float*)d_out;                   // (8,64,64,64)

    cudaFuncSetAttribute(depthconv_mma,
                         cudaFuncAttributeMaxDynamicSharedMemorySize,
                         SMEM_TOTAL);

    prep_all<<<NT_BLK + NW_BLK, 256>>>(x, w);
    depthconv_mma<<<Bn * 32, 256, SMEM_TOTAL>>>(depth, out);
}